// round 4
// baseline (speedup 1.0000x reference)
#include <cuda_runtime.h>
#include <math.h>

#define BB 8
#define NN 2048
#define FF 128
#define NWRD (NN / 32)   // 64 bitmask words per row

// ---------------- scratch (device globals; no allocations allowed) ----------
__device__ float    g_c[FF];                  // c = W @ a_i
__device__ float    g_u[BB * NN];             // u = exp(X @ c)
__device__ float    g_w[BB * NN];             // w = A @ u
__device__ float    g_xpart[BB * 128 * FF];   // per-block partial col-sums of X
__device__ float    g_S[BB * FF];             // S = (sum_n X) @ W
__device__ unsigned g_bits[BB * NN * NWRD];   // A != 0 bitmask (4 MB)

// ---------------- k0: c[fi] = sum_o W[fi,o] * a[128+o]  (warp per fi) -------
__global__ void k0_c(const float* __restrict__ W, const float* __restrict__ a)
{
    const int warp = (blockIdx.x * 1024 + threadIdx.x) >> 5;  // = fi
    const int lane = threadIdx.x & 31;

    float4 w4 = reinterpret_cast<const float4*>(W + warp * FF)[lane];
    float4 a4 = reinterpret_cast<const float4*>(a + FF)[lane];   // a_i
    float s = w4.x * a4.x + w4.y * a4.y + w4.z * a4.z + w4.w * a4.w;
#pragma unroll
    for (int off = 16; off; off >>= 1)
        s += __shfl_xor_sync(0xffffffffu, s, off);
    if (lane == 0) g_c[warp] = s;
}

// ---------------- k1: u = exp(X @ c); per-block partial column-sums of X ----
// grid (128, 8), block 512 (16 warps, 1 row per warp)
__global__ void k1_u_xsum(const float* __restrict__ X)
{
    const int b    = blockIdx.y;
    const int warp = threadIdx.x >> 5;
    const int lane = threadIdx.x & 31;

    __shared__ float sc[FF];
    __shared__ float sx[16][FF];
    if (threadIdx.x < FF) sc[threadIdx.x] = g_c[threadIdx.x];
    __syncthreads();

    const int row = blockIdx.x * 16 + warp;
    float4 x4 = reinterpret_cast<const float4*>(
                    X + ((size_t)b * NN + row) * FF)[lane];
    float4 c4 = reinterpret_cast<const float4*>(sc)[lane];

    float s = x4.x * c4.x + x4.y * c4.y + x4.z * c4.z + x4.w * c4.w;
#pragma unroll
    for (int off = 16; off; off >>= 1)
        s += __shfl_xor_sync(0xffffffffu, s, off);
    if (lane == 0) g_u[(size_t)b * NN + row] = expf(s);

    reinterpret_cast<float4*>(sx[warp])[lane] = x4;
    __syncthreads();
    if (threadIdx.x < FF) {
        float v = 0.f;
#pragma unroll
        for (int w2 = 0; w2 < 16; w2++) v += sx[w2][threadIdx.x];
        g_xpart[((size_t)b * 128 + blockIdx.x) * FF + threadIdx.x] = v;
    }
}

// ---------------- k3: w = A @ u + bitmask(A != 0) + (fused) S ---------------
// grid (129, 8), block 512. Blocks 0..127: 16 rows each, 8-deep prefetch.
// Default caching: A (134MB) stays mostly L2-resident across graph replays.
// Bit layout: word w (0..63): j = w>>2, c = w&3; bit t <-> column j*128+t*4+c
__global__ void __launch_bounds__(512) k3_w_bits_S(const float* __restrict__ A,
                                                   const float* __restrict__ W)
{
    const int b = blockIdx.y;

    if (blockIdx.x == 128) {
        // ---- S path: xs = sum over 128 chunks of g_xpart; S = xs @ W ----
        __shared__ float part[4][FF];
        __shared__ float xs[FF];
        __shared__ float dot[4][FF];
        const int t = threadIdx.x & 127;
        const int p = threadIdx.x >> 7;          // 0..3
        float v = 0.f;
#pragma unroll 8
        for (int c = 0; c < 32; c++)
            v += g_xpart[((size_t)b * 128 + p * 32 + c) * FF + t];
        part[p][t] = v;
        __syncthreads();
        if (threadIdx.x < FF)
            xs[t] = part[0][t] + part[1][t] + part[2][t] + part[3][t];
        __syncthreads();
        float s = 0.f;
#pragma unroll 8
        for (int k = 0; k < 32; k++) {
            const int fi = p * 32 + k;
            s += xs[fi] * W[fi * FF + t];
        }
        dot[p][t] = s;
        __syncthreads();
        if (threadIdx.x < FF)
            g_S[b * FF + t] = dot[0][t] + dot[1][t] + dot[2][t] + dot[3][t];
        return;
    }

    __shared__ float su[NN];
    for (int i = threadIdx.x; i < NN; i += 512) su[i] = g_u[(size_t)b * NN + i];
    __syncthreads();

    const int warp = threadIdx.x >> 5;
    const int lane = threadIdx.x & 31;
    const int row  = blockIdx.x * 16 + warp;

    const float4* Ar = reinterpret_cast<const float4*>(
                           A + ((size_t)(b * NN + row)) * NN);
    const float4* su4 = reinterpret_cast<const float4*>(su);

    const int jmine0 = lane >> 2;        // word lane      -> j = lane>>2
    const int jmine1 = 8 + (lane >> 2);  // word lane+32   -> j = 8+(lane>>2)
    const int c      = lane & 3;

    float ax = 0.f, ay = 0.f, az = 0.f, aw = 0.f;
    unsigned w0 = 0u, w1 = 0u;

#pragma unroll
    for (int half = 0; half < 2; half++) {
        float4 v[8];
#pragma unroll
        for (int k = 0; k < 8; k++)          // 8 LDG.128 in flight per warp
            v[k] = Ar[(half * 8 + k) * 32 + lane];
#pragma unroll
        for (int k = 0; k < 8; k++) {
            const int j = half * 8 + k;
            float4 s4 = su4[j * 32 + lane];
            unsigned b0 = __ballot_sync(0xffffffffu, v[k].x != 0.f);
            unsigned b1 = __ballot_sync(0xffffffffu, v[k].y != 0.f);
            unsigned b2 = __ballot_sync(0xffffffffu, v[k].z != 0.f);
            unsigned b3 = __ballot_sync(0xffffffffu, v[k].w != 0.f);
            ax += v[k].x * s4.x;
            ay += v[k].y * s4.y;
            az += v[k].z * s4.z;
            aw += v[k].w * s4.w;
            unsigned bs = (c == 0) ? b0 : (c == 1) ? b1 : (c == 2) ? b2 : b3;
            if (j == jmine0) w0 = bs;
            if (j == jmine1) w1 = bs;
        }
    }

    float acc = (ax + ay) + (az + aw);
#pragma unroll
    for (int off = 16; off; off >>= 1)
        acc += __shfl_xor_sync(0xffffffffu, acc, off);

    unsigned* br = g_bits + ((size_t)(b * NN + row)) * NWRD;
    br[lane]      = w0;
    br[32 + lane] = w1;
    if (lane == 0) g_w[(size_t)b * NN + row] = acc;
}

// ---------------- k5: q = A @ r via nibble-LUT; H = q*S + bias_W ------------
// grid (64, 8), block 512. Each block: 32 rows (2 per warp).
// tab[G][v] = sum of r over the subset v of group G's 4 columns.
// Group G (0..511): w = G>>3, n = G&7; columns (w>>2)*128 + (w&3) + 16n + 4*{0..3}
__global__ void __launch_bounds__(512) k5_out(float* __restrict__ H,
                                              const float* __restrict__ biasW)
{
    const int b = blockIdx.y;
    __shared__ float sr[NN];            // 8 KB
    __shared__ float tab[512 * 17];     // 34.8 KB (17-pad: bank-conflict-free)
    __shared__ float sS[FF];
    __shared__ float sbw[FF];

    for (int i = threadIdx.x; i < NN; i += 512) {
        float u = g_u[(size_t)b * NN + i];
        float w = g_w[(size_t)b * NN + i];
        sr[i] = (w != 0.f) ? __fdividef(u, w) : 0.f;  // r, num==0 guard
    }
    if (threadIdx.x < FF) {
        sS[threadIdx.x]  = g_S[b * FF + threadIdx.x];
        sbw[threadIdx.x] = biasW[threadIdx.x];
    }
    __syncthreads();

    {   // build LUT: thread g owns group g
        const int g  = threadIdx.x;
        const int w  = g >> 3, n = g & 7;
        const int cb = (w >> 2) * 128 + (w & 3) + 16 * n;
        const float s0 = sr[cb], s1 = sr[cb + 4], s2 = sr[cb + 8], s3 = sr[cb + 12];
        float* T = tab + g * 17;
        const float s01 = s0 + s1;
        T[0]  = 0.f;       T[1]  = s0;        T[2]  = s1;        T[3]  = s01;
        T[4]  = s2;        T[5]  = s0 + s2;   T[6]  = s1 + s2;   T[7]  = s01 + s2;
        T[8]  = s3;        T[9]  = s0 + s3;   T[10] = s1 + s3;   T[11] = s01 + s3;
        T[12] = s2 + s3;   T[13] = s0 + s2 + s3; T[14] = s1 + s2 + s3;
        T[15] = s01 + s2 + s3;
    }
    __syncthreads();

    const int warp = threadIdx.x >> 5;
    const int lane = threadIdx.x & 31;
    const int row0 = blockIdx.x * 32 + warp * 2;       // this warp: row0, row0+1

    const unsigned* brA = g_bits + ((size_t)(b * NN + row0)) * NWRD;
    const unsigned a0 = brA[lane];          // words 0..31 of row0
    const unsigned a1 = brA[32 + lane];     // words 32..63
    const unsigned b0m = brA[NWRD + lane];         // row0+1
    const unsigned b1m = brA[NWRD + 32 + lane];

    const int myshift = 4 * (lane & 7);     // nibble within word (n = lane&7)
    const int src     = lane >> 3;          // word = 4k + src

    float accA0 = 0.f, accA1 = 0.f, accB0 = 0.f, accB1 = 0.f;
#pragma unroll
    for (int k = 0; k < 8; k++) {
        const unsigned wa0 = __shfl_sync(0xffffffffu, a0,  4 * k + src);
        const unsigned wa1 = __shfl_sync(0xffffffffu, a1,  4 * k + src);
        const unsigned wb0 = __shfl_sync(0xffffffffu, b0m, 4 * k + src);
        const unsigned wb1 = __shfl_sync(0xffffffffu, b1m, 4 * k + src);
        const float* T0 = tab + (32 * k + lane) * 17;          // G = 32k+lane
        const float* T1 = tab + (32 * (k + 8) + lane) * 17;    // G = 32(k+8)+lane
        accA0 += T0[(wa0 >> myshift) & 15u];
        accA1 += T1[(wa1 >> myshift) & 15u];
        accB0 += T0[(wb0 >> myshift) & 15u];
        accB1 += T1[(wb1 >> myshift) & 15u];
    }
    float accA = accA0 + accA1;
    float accB = accB0 + accB1;
#pragma unroll
    for (int off = 16; off; off >>= 1) {
        accA += __shfl_xor_sync(0xffffffffu, accA, off);   // q[row0]
        accB += __shfl_xor_sync(0xffffffffu, accB, off);   // q[row0+1]
    }

    const float4 s4 = reinterpret_cast<const float4*>(sS)[lane];
    const float4 w4 = reinterpret_cast<const float4*>(sbw)[lane];
    float4 oA, oB;
    oA.x = accA * s4.x + w4.x;  oA.y = accA * s4.y + w4.y;
    oA.z = accA * s4.z + w4.z;  oA.w = accA * s4.w + w4.w;
    oB.x = accB * s4.x + w4.x;  oB.y = accB * s4.y + w4.y;
    oB.z = accB * s4.z + w4.z;  oB.w = accB * s4.w + w4.w;
    reinterpret_cast<float4*>(H + ((size_t)(b * NN + row0)) * FF)[lane]      = oA;
    reinterpret_cast<float4*>(H + ((size_t)(b * NN + row0 + 1)) * FF)[lane]  = oB;
}

// ---------------- launch -----------------------------------------------------
extern "C" void kernel_launch(void* const* d_in, const int* in_sizes, int n_in,
                              void* d_out, int out_size)
{
    const float* X     = (const float*)d_in[0];
    const float* A     = (const float*)d_in[1];
    const float* W     = (const float*)d_in[2];
    const float* a     = (const float*)d_in[3];
    // d_in[4] = bias_a: cancels analytically (rank-1 den), unused.
    const float* biasW = (const float*)d_in[5];
    float* H = (float*)d_out;

    k0_c       <<<4, 1024>>>(W, a);
    k1_u_xsum  <<<dim3(128, BB), 512>>>(X);
    k3_w_bits_S<<<dim3(129, BB), 512>>>(A, W);
    k5_out     <<<dim3(64, BB), 512>>>(H, biasW);
}

// round 5
// speedup vs baseline: 1.0984x; 1.0984x over previous
#include <cuda_runtime.h>
#include <math.h>

#define BB 8
#define NN 2048
#define FF 128
#define NWRD (NN / 32)   // 64 bitmask words per row

// ---------------- scratch (device globals; no allocations allowed) ----------
__device__ float    g_c[FF];                  // c = W @ a_i
__device__ float    g_u[BB * NN];             // u = exp(X @ c)
__device__ float    g_w[BB * NN];             // w = A @ u
__device__ float    g_xpart[BB * 128 * FF];   // per-block partial col-sums of X
__device__ float    g_S[BB * FF];             // S = (sum_n X) @ W
__device__ unsigned g_bits[BB * NN * NWRD];   // A != 0 bitmask (4 MB)

// ---------------- k0: c[fi] = sum_o W[fi,o] * a[128+o]  (warp per fi) -------
__global__ void k0_c(const float* __restrict__ W, const float* __restrict__ a)
{
    const int warp = (blockIdx.x * 1024 + threadIdx.x) >> 5;  // = fi
    const int lane = threadIdx.x & 31;

    float4 w4 = reinterpret_cast<const float4*>(W + warp * FF)[lane];
    float4 a4 = reinterpret_cast<const float4*>(a + FF)[lane];   // a_i
    float s = w4.x * a4.x + w4.y * a4.y + w4.z * a4.z + w4.w * a4.w;
#pragma unroll
    for (int off = 16; off; off >>= 1)
        s += __shfl_xor_sync(0xffffffffu, s, off);
    if (lane == 0) g_c[warp] = s;
}

// ---------------- k1: u = exp(X @ c); per-block partial column-sums of X ----
// grid (128, 8), block 512 (16 warps, 1 row per warp)
__global__ void k1_u_xsum(const float* __restrict__ X)
{
    const int b    = blockIdx.y;
    const int warp = threadIdx.x >> 5;
    const int lane = threadIdx.x & 31;

    __shared__ float sc[FF];
    __shared__ float sx[16][FF];
    if (threadIdx.x < FF) sc[threadIdx.x] = g_c[threadIdx.x];
    __syncthreads();

    const int row = blockIdx.x * 16 + warp;
    float4 x4 = reinterpret_cast<const float4*>(
                    X + ((size_t)b * NN + row) * FF)[lane];
    float4 c4 = reinterpret_cast<const float4*>(sc)[lane];

    float s = x4.x * c4.x + x4.y * c4.y + x4.z * c4.z + x4.w * c4.w;
#pragma unroll
    for (int off = 16; off; off >>= 1)
        s += __shfl_xor_sync(0xffffffffu, s, off);
    if (lane == 0) g_u[(size_t)b * NN + row] = expf(s);

    reinterpret_cast<float4*>(sx[warp])[lane] = x4;
    __syncthreads();
    if (threadIdx.x < FF) {
        float v = 0.f;
#pragma unroll
        for (int w2 = 0; w2 < 16; w2++) v += sx[w2][threadIdx.x];
        g_xpart[((size_t)b * 128 + blockIdx.x) * FF + threadIdx.x] = v;
    }
}

// ---------------- k3: w = A @ u + bitmask(A != 0) + (fused) S ---------------
// grid (129, 8), block 512. Blocks 0..127: 16 rows each, 8-deep prefetch,
// __ldcs streaming (A has zero reuse; keep it out of L2's way).
// Bit layout: word w (0..63): j = w>>2, c = w&3; bit t <-> column j*128+t*4+c
__global__ void __launch_bounds__(512) k3_w_bits_S(const float* __restrict__ A,
                                                   const float* __restrict__ W)
{
    const int b = blockIdx.y;

    if (blockIdx.x == 128) {
        // ---- S path: xs = sum over 128 chunks of g_xpart; S = xs @ W ----
        __shared__ float part[4][FF];
        __shared__ float xs[FF];
        __shared__ float dot[4][FF];
        const int t = threadIdx.x & 127;
        const int p = threadIdx.x >> 7;          // 0..3
        float v = 0.f;
#pragma unroll 8
        for (int c = 0; c < 32; c++)
            v += g_xpart[((size_t)b * 128 + p * 32 + c) * FF + t];
        part[p][t] = v;
        __syncthreads();
        if (threadIdx.x < FF)
            xs[t] = part[0][t] + part[1][t] + part[2][t] + part[3][t];
        __syncthreads();
        float s = 0.f;
#pragma unroll 8
        for (int k = 0; k < 32; k++) {
            const int fi = p * 32 + k;
            s += xs[fi] * W[fi * FF + t];
        }
        dot[p][t] = s;
        __syncthreads();
        if (threadIdx.x < FF)
            g_S[b * FF + t] = dot[0][t] + dot[1][t] + dot[2][t] + dot[3][t];
        return;
    }

    __shared__ float su[NN];
    for (int i = threadIdx.x; i < NN; i += 512) su[i] = g_u[(size_t)b * NN + i];
    __syncthreads();

    const int warp = threadIdx.x >> 5;
    const int lane = threadIdx.x & 31;
    const int row  = blockIdx.x * 16 + warp;

    const float4* Ar = reinterpret_cast<const float4*>(
                           A + ((size_t)(b * NN + row)) * NN);
    const float4* su4 = reinterpret_cast<const float4*>(su);

    const int jmine0 = lane >> 2;        // word lane      -> j = lane>>2
    const int jmine1 = 8 + (lane >> 2);  // word lane+32   -> j = 8+(lane>>2)
    const int c      = lane & 3;

    float ax = 0.f, ay = 0.f, az = 0.f, aw = 0.f;
    unsigned w0 = 0u, w1 = 0u;

#pragma unroll
    for (int half = 0; half < 2; half++) {
        float4 v[8];
#pragma unroll
        for (int k = 0; k < 8; k++)          // 8 LDG.128 in flight per warp
            v[k] = __ldcs(&Ar[(half * 8 + k) * 32 + lane]);
#pragma unroll
        for (int k = 0; k < 8; k++) {
            const int j = half * 8 + k;
            float4 s4 = su4[j * 32 + lane];
            unsigned b0 = __ballot_sync(0xffffffffu, v[k].x != 0.f);
            unsigned b1 = __ballot_sync(0xffffffffu, v[k].y != 0.f);
            unsigned b2 = __ballot_sync(0xffffffffu, v[k].z != 0.f);
            unsigned b3 = __ballot_sync(0xffffffffu, v[k].w != 0.f);
            ax += v[k].x * s4.x;
            ay += v[k].y * s4.y;
            az += v[k].z * s4.z;
            aw += v[k].w * s4.w;
            unsigned bs = (c == 0) ? b0 : (c == 1) ? b1 : (c == 2) ? b2 : b3;
            if (j == jmine0) w0 = bs;
            if (j == jmine1) w1 = bs;
        }
    }

    float acc = (ax + ay) + (az + aw);
#pragma unroll
    for (int off = 16; off; off >>= 1)
        acc += __shfl_xor_sync(0xffffffffu, acc, off);

    unsigned* br = g_bits + ((size_t)(b * NN + row)) * NWRD;
    br[lane]      = w0;
    br[32 + lane] = w1;
    if (lane == 0) g_w[(size_t)b * NN + row] = acc;
}

// ---------------- k5: q = A @ r via nibble-LUT; H = q*S + bias_W ------------
// grid (64, 8), block 512. Each block: 32 rows (2 per warp).
// tab[v][G] (subset-major): lookup addr = v*512 + G, G = 32k+lane
//   -> bank = lane for every lane, every k, every data value: conflict-free.
// Group G (0..511): w = G>>3, n = G&7; columns (w>>2)*128 + (w&3) + 16n + 4*{0..3}
__global__ void __launch_bounds__(512) k5_out(float* __restrict__ H,
                                              const float* __restrict__ biasW)
{
    const int b = blockIdx.y;
    __shared__ float sr[NN];            // 8 KB
    __shared__ float tab[16][512];      // 32 KB, subset-major
    __shared__ float sS[FF];
    __shared__ float sbw[FF];

    for (int i = threadIdx.x; i < NN; i += 512) {
        float u = g_u[(size_t)b * NN + i];
        float w = g_w[(size_t)b * NN + i];
        sr[i] = (w != 0.f) ? __fdividef(u, w) : 0.f;  // r, num==0 guard
    }
    if (threadIdx.x < FF) {
        sS[threadIdx.x]  = g_S[b * FF + threadIdx.x];
        sbw[threadIdx.x] = biasW[threadIdx.x];
    }
    __syncthreads();

    {   // build LUT: thread g owns group g (writes stride-512 -> bank g, CF)
        const int g  = threadIdx.x;
        const int w  = g >> 3, n = g & 7;
        const int cb = (w >> 2) * 128 + (w & 3) + 16 * n;
        const float s0 = sr[cb], s1 = sr[cb + 4], s2 = sr[cb + 8], s3 = sr[cb + 12];
        const float s01 = s0 + s1;
        const float s23 = s2 + s3;
        tab[0][g]  = 0.f;        tab[1][g]  = s0;         tab[2][g]  = s1;
        tab[3][g]  = s01;        tab[4][g]  = s2;         tab[5][g]  = s0 + s2;
        tab[6][g]  = s1 + s2;    tab[7][g]  = s01 + s2;   tab[8][g]  = s3;
        tab[9][g]  = s0 + s3;    tab[10][g] = s1 + s3;    tab[11][g] = s01 + s3;
        tab[12][g] = s23;        tab[13][g] = s0 + s23;   tab[14][g] = s1 + s23;
        tab[15][g] = s01 + s23;
    }
    __syncthreads();

    const int warp = threadIdx.x >> 5;
    const int lane = threadIdx.x & 31;
    const int row0 = blockIdx.x * 32 + warp * 2;       // this warp: row0, row0+1

    const unsigned* brA = g_bits + ((size_t)(b * NN + row0)) * NWRD;
    const unsigned a0 = brA[lane];          // words 0..31 of row0
    const unsigned a1 = brA[32 + lane];     // words 32..63
    const unsigned b0m = brA[NWRD + lane];         // row0+1
    const unsigned b1m = brA[NWRD + 32 + lane];

    const int myshift = 4 * (lane & 7);     // nibble within word (n = lane&7)
    const int src     = lane >> 3;          // word = 4k + src

    const float* tb = &tab[0][0];
    float accA0 = 0.f, accA1 = 0.f, accB0 = 0.f, accB1 = 0.f;
#pragma unroll
    for (int k = 0; k < 8; k++) {
        const unsigned wa0 = __shfl_sync(0xffffffffu, a0,  4 * k + src);
        const unsigned wa1 = __shfl_sync(0xffffffffu, a1,  4 * k + src);
        const unsigned wb0 = __shfl_sync(0xffffffffu, b0m, 4 * k + src);
        const unsigned wb1 = __shfl_sync(0xffffffffu, b1m, 4 * k + src);
        const int G0 = 32 * k + lane;            // group for word 4k+src
        const int G1 = 32 * (k + 8) + lane;
        accA0 += tb[((wa0 >> myshift) & 15u) * 512 + G0];
        accA1 += tb[((wa1 >> myshift) & 15u) * 512 + G1];
        accB0 += tb[((wb0 >> myshift) & 15u) * 512 + G0];
        accB1 += tb[((wb1 >> myshift) & 15u) * 512 + G1];
    }
    float accA = accA0 + accA1;
    float accB = accB0 + accB1;
#pragma unroll
    for (int off = 16; off; off >>= 1) {
        accA += __shfl_xor_sync(0xffffffffu, accA, off);   // q[row0]
        accB += __shfl_xor_sync(0xffffffffu, accB, off);   // q[row0+1]
    }

    const float4 s4 = reinterpret_cast<const float4*>(sS)[lane];
    const float4 w4 = reinterpret_cast<const float4*>(sbw)[lane];
    float4 oA, oB;
    oA.x = accA * s4.x + w4.x;  oA.y = accA * s4.y + w4.y;
    oA.z = accA * s4.z + w4.z;  oA.w = accA * s4.w + w4.w;
    oB.x = accB * s4.x + w4.x;  oB.y = accB * s4.y + w4.y;
    oB.z = accB * s4.z + w4.z;  oB.w = accB * s4.w + w4.w;
    reinterpret_cast<float4*>(H + ((size_t)(b * NN + row0)) * FF)[lane]      = oA;
    reinterpret_cast<float4*>(H + ((size_t)(b * NN + row0 + 1)) * FF)[lane]  = oB;
}

// ---------------- launch -----------------------------------------------------
extern "C" void kernel_launch(void* const* d_in, const int* in_sizes, int n_in,
                              void* d_out, int out_size)
{
    const float* X     = (const float*)d_in[0];
    const float* A     = (const float*)d_in[1];
    const float* W     = (const float*)d_in[2];
    const float* a     = (const float*)d_in[3];
    // d_in[4] = bias_a: cancels analytically (rank-1 den), unused.
    const float* biasW = (const float*)d_in[5];
    float* H = (float*)d_out;

    k0_c       <<<4, 1024>>>(W, a);
    k1_u_xsum  <<<dim3(128, BB), 512>>>(X);
    k3_w_bits_S<<<dim3(129, BB), 512>>>(A, W);
    k5_out     <<<dim3(64, BB), 512>>>(H, biasW);
}

// round 6
// speedup vs baseline: 1.1346x; 1.0329x over previous
#include <cuda_runtime.h>
#include <math.h>

#define BB 8
#define NN 2048
#define FF 128
#define NWRD (NN / 32)   // 64 bitmask words per row

// ---------------- scratch (device globals; no allocations allowed) ----------
__device__ float    g_c[FF];                  // c = W @ a_i
__device__ float    g_u[BB * NN];             // u = exp(X @ c)
__device__ float    g_w[BB * NN];             // w = A @ u
__device__ float    g_xpart[BB * 128 * FF];   // per-block partial col-sums of X
__device__ float    g_S[BB * FF];             // S = (sum_n X) @ W
__device__ unsigned g_bits[BB * NN * NWRD];   // A != 0 bitmask (4 MB)
// Bit layout (lane-local; no cross-lane ops needed anywhere):
//   word w (0..63): L = w&31, half = w>>5; nibble j' (0..7) of word w
//   covers columns (half*8+j')*128 + L*4 + {0..3}

// ---------------- k0: c[fi] = sum_o W[fi,o] * a[128+o]  (warp per fi) -------
__global__ void k0_c(const float* __restrict__ W, const float* __restrict__ a)
{
    const int warp = (blockIdx.x * 1024 + threadIdx.x) >> 5;  // = fi
    const int lane = threadIdx.x & 31;

    float4 w4 = reinterpret_cast<const float4*>(W + warp * FF)[lane];
    float4 a4 = reinterpret_cast<const float4*>(a + FF)[lane];   // a_i
    float s = w4.x * a4.x + w4.y * a4.y + w4.z * a4.z + w4.w * a4.w;
#pragma unroll
    for (int off = 16; off; off >>= 1)
        s += __shfl_xor_sync(0xffffffffu, s, off);
    if (lane == 0) g_c[warp] = s;
}

// ---------------- k1: u = exp(X @ c); per-block partial column-sums of X ----
// grid (128, 8), block 512 (16 warps, 1 row per warp)
__global__ void k1_u_xsum(const float* __restrict__ X)
{
    const int b    = blockIdx.y;
    const int warp = threadIdx.x >> 5;
    const int lane = threadIdx.x & 31;

    __shared__ float sc[FF];
    __shared__ float sx[16][FF];
    if (threadIdx.x < FF) sc[threadIdx.x] = g_c[threadIdx.x];
    __syncthreads();

    const int row = blockIdx.x * 16 + warp;
    float4 x4 = reinterpret_cast<const float4*>(
                    X + ((size_t)b * NN + row) * FF)[lane];
    float4 c4 = reinterpret_cast<const float4*>(sc)[lane];

    float s = x4.x * c4.x + x4.y * c4.y + x4.z * c4.z + x4.w * c4.w;
#pragma unroll
    for (int off = 16; off; off >>= 1)
        s += __shfl_xor_sync(0xffffffffu, s, off);
    if (lane == 0) g_u[(size_t)b * NN + row] = expf(s);

    reinterpret_cast<float4*>(sx[warp])[lane] = x4;
    __syncthreads();
    if (threadIdx.x < FF) {
        float v = 0.f;
#pragma unroll
        for (int w2 = 0; w2 < 16; w2++) v += sx[w2][threadIdx.x];
        g_xpart[((size_t)b * 128 + blockIdx.x) * FF + threadIdx.x] = v;
    }
}

// ---------------- k3: w = A @ u + bitmask(A != 0) + (fused) S ---------------
// grid (129, 8), block 512. Blocks 0..127: 16 rows each, 8-deep prefetch,
// __ldcs streaming. Lane-local nibble encode: NO ballots.
__global__ void __launch_bounds__(512) k3_w_bits_S(const float* __restrict__ A,
                                                   const float* __restrict__ W)
{
    const int b = blockIdx.y;

    if (blockIdx.x == 128) {
        // ---- S path: xs = sum over 128 chunks of g_xpart; S = xs @ W ----
        __shared__ float part[4][FF];
        __shared__ float xs[FF];
        __shared__ float dot[4][FF];
        const int t = threadIdx.x & 127;
        const int p = threadIdx.x >> 7;          // 0..3
        float v = 0.f;
#pragma unroll 8
        for (int c = 0; c < 32; c++)
            v += g_xpart[((size_t)b * 128 + p * 32 + c) * FF + t];
        part[p][t] = v;
        __syncthreads();
        if (threadIdx.x < FF)
            xs[t] = part[0][t] + part[1][t] + part[2][t] + part[3][t];
        __syncthreads();
        float s = 0.f;
#pragma unroll 8
        for (int k = 0; k < 32; k++) {
            const int fi = p * 32 + k;
            s += xs[fi] * W[fi * FF + t];
        }
        dot[p][t] = s;
        __syncthreads();
        if (threadIdx.x < FF)
            g_S[b * FF + t] = dot[0][t] + dot[1][t] + dot[2][t] + dot[3][t];
        return;
    }

    __shared__ float su[NN];
    for (int i = threadIdx.x; i < NN; i += 512) su[i] = g_u[(size_t)b * NN + i];
    __syncthreads();

    const int warp = threadIdx.x >> 5;
    const int lane = threadIdx.x & 31;
    const int row  = blockIdx.x * 16 + warp;

    const float4* Ar = reinterpret_cast<const float4*>(
                           A + ((size_t)(b * NN + row)) * NN);
    const float4* su4 = reinterpret_cast<const float4*>(su);

    float ax = 0.f, ay = 0.f, az = 0.f, aw = 0.f;
    unsigned w0 = 0u, w1 = 0u;

#pragma unroll
    for (int half = 0; half < 2; half++) {
        float4 v[8];
#pragma unroll
        for (int k = 0; k < 8; k++)          // 8 LDG.128 in flight per warp
            v[k] = __ldcs(&Ar[(half * 8 + k) * 32 + lane]);
#pragma unroll
        for (int k = 0; k < 8; k++) {
            const int j = half * 8 + k;
            float4 s4 = su4[j * 32 + lane];
            unsigned nib = (unsigned)(v[k].x != 0.f)
                         + 2u * (unsigned)(v[k].y != 0.f)
                         + 4u * (unsigned)(v[k].z != 0.f)
                         + 8u * (unsigned)(v[k].w != 0.f);
            if (half == 0) w0 |= nib << (4 * k);
            else           w1 |= nib << (4 * k);
            ax += v[k].x * s4.x;
            ay += v[k].y * s4.y;
            az += v[k].z * s4.z;
            aw += v[k].w * s4.w;
        }
    }

    float acc = (ax + ay) + (az + aw);
#pragma unroll
    for (int off = 16; off; off >>= 1)
        acc += __shfl_xor_sync(0xffffffffu, acc, off);

    unsigned* br = g_bits + ((size_t)(b * NN + row)) * NWRD;
    br[lane]      = w0;    // columns j*128 + lane*4 + {0..3}, j = 0..7
    br[32 + lane] = w1;    // j = 8..15
    if (lane == 0) g_w[(size_t)b * NN + row] = acc;
}

// ---------------- k5: q = A @ r via nibble-LUT; H = q*S + bias_W ------------
// grid (32, 8), block 512. Each block: 64 rows (4 per warp).
// tab[v][G], G = j*32 + L: lookup addr = v*512 + j*32 + lane -> bank = lane,
// conflict-free for any data; decode is fully lane-local (no shuffles).
__global__ void __launch_bounds__(512) k5_out(float* __restrict__ H,
                                              const float* __restrict__ biasW)
{
    const int b = blockIdx.y;
    __shared__ float sr[NN];            // 8 KB
    __shared__ float tab[16][512];      // 32 KB, subset-major
    __shared__ float sS[FF];
    __shared__ float sbw[FF];

    for (int i = threadIdx.x; i < NN; i += 512) {
        float u = g_u[(size_t)b * NN + i];
        float w = g_w[(size_t)b * NN + i];
        sr[i] = (w != 0.f) ? __fdividef(u, w) : 0.f;  // r, num==0 guard
    }
    if (threadIdx.x < FF) {
        sS[threadIdx.x]  = g_S[b * FF + threadIdx.x];
        sbw[threadIdx.x] = biasW[threadIdx.x];
    }
    __syncthreads();

    {   // build LUT: thread g owns group G = g = j*32 + L  (cb = 4g -> float4)
        const int g = threadIdx.x;
        const float4 s = reinterpret_cast<const float4*>(sr)[g];
        const float s01 = s.x + s.y;
        const float s23 = s.z + s.w;
        tab[0][g]  = 0.f;          tab[1][g]  = s.x;          tab[2][g]  = s.y;
        tab[3][g]  = s01;          tab[4][g]  = s.z;          tab[5][g]  = s.x + s.z;
        tab[6][g]  = s.y + s.z;    tab[7][g]  = s01 + s.z;    tab[8][g]  = s.w;
        tab[9][g]  = s.x + s.w;    tab[10][g] = s.y + s.w;    tab[11][g] = s01 + s.w;
        tab[12][g] = s23;          tab[13][g] = s.x + s23;    tab[14][g] = s.y + s23;
        tab[15][g] = s01 + s23;
    }
    __syncthreads();

    const int warp = threadIdx.x >> 5;
    const int lane = threadIdx.x & 31;
    const int row0 = blockIdx.x * 64 + warp * 4;     // 4 rows per warp

    const unsigned* bb = g_bits + ((size_t)(b * NN + row0)) * NWRD;
    unsigned rw0[4], rw1[4];
#pragma unroll
    for (int r = 0; r < 4; r++) {
        rw0[r] = bb[r * NWRD + lane];        // half 0: j = 0..7
        rw1[r] = bb[r * NWRD + 32 + lane];   // half 1: j = 8..15
    }

    const float* tb = &tab[0][0];
    float accA[4] = {0.f, 0.f, 0.f, 0.f};
    float accB[4] = {0.f, 0.f, 0.f, 0.f};
#pragma unroll
    for (int j = 0; j < 8; j++) {
        const int base0 = j * 32 + lane;            // G for half 0
        const int base1 = (8 + j) * 32 + lane;      // G for half 1
#pragma unroll
        for (int r = 0; r < 4; r++) {
            accA[r] += tb[((rw0[r] >> (4 * j)) & 15u) * 512 + base0];
            accB[r] += tb[((rw1[r] >> (4 * j)) & 15u) * 512 + base1];
        }
    }

    const float4 s4 = reinterpret_cast<const float4*>(sS)[lane];
    const float4 w4 = reinterpret_cast<const float4*>(sbw)[lane];
#pragma unroll
    for (int r = 0; r < 4; r++) {
        float acc = accA[r] + accB[r];
#pragma unroll
        for (int off = 16; off; off >>= 1)
            acc += __shfl_xor_sync(0xffffffffu, acc, off);   // q[row0+r]
        float4 o;
        o.x = acc * s4.x + w4.x;
        o.y = acc * s4.y + w4.y;
        o.z = acc * s4.z + w4.z;
        o.w = acc * s4.w + w4.w;
        reinterpret_cast<float4*>(H + ((size_t)(b * NN + row0 + r)) * FF)[lane] = o;
    }
}

// ---------------- launch -----------------------------------------------------
extern "C" void kernel_launch(void* const* d_in, const int* in_sizes, int n_in,
                              void* d_out, int out_size)
{
    const float* X     = (const float*)d_in[0];
    const float* A     = (const float*)d_in[1];
    const float* W     = (const float*)d_in[2];
    const float* a     = (const float*)d_in[3];
    // d_in[4] = bias_a: cancels analytically (rank-1 den), unused.
    const float* biasW = (const float*)d_in[5];
    float* H = (float*)d_out;

    k0_c       <<<4, 1024>>>(W, a);
    k1_u_xsum  <<<dim3(128, BB), 512>>>(X);
    k3_w_bits_S<<<dim3(129, BB), 512>>>(A, W);
    k5_out     <<<dim3(32, BB), 512>>>(H, biasW);
}

// round 7
// speedup vs baseline: 1.3290x; 1.1714x over previous
#include <cuda_runtime.h>
#include <math.h>

#define BB 8
#define NN 2048
#define FF 128
#define NWRD (NN / 32)   // 64 bitmask words per row

// ---------------- scratch (device globals; no allocations allowed) ----------
__device__ float    g_c[FF];                  // c = W @ a_i
__device__ float    g_u[BB * NN];             // u = exp(X @ c)
__device__ float    g_r[BB * NN];             // r = u / (A@u)   (att row value)
__device__ float    g_xpart[BB * 128 * FF];   // per-block partial col-sums of X
__device__ float    g_S[BB * FF];             // S = (sum_n X) @ W
__device__ unsigned g_bits[BB * NN * NWRD];   // A != 0 bitmask (4 MB)
// Bit layout (lane-local): word w (0..63): L = w&31, half = w>>5;
//   nibble j' (0..7) of word w covers columns (half*8+j')*128 + L*4 + {0..3}

// ---------------- k0: c[fi] = sum_o W[fi,o] * a[128+o]  (warp per fi) -------
__global__ void k0_c(const float* __restrict__ W, const float* __restrict__ a)
{
    const int warp = (blockIdx.x * 1024 + threadIdx.x) >> 5;  // = fi
    const int lane = threadIdx.x & 31;

    float4 w4 = reinterpret_cast<const float4*>(W + warp * FF)[lane];
    float4 a4 = reinterpret_cast<const float4*>(a + FF)[lane];   // a_i
    float s = w4.x * a4.x + w4.y * a4.y + w4.z * a4.z + w4.w * a4.w;
#pragma unroll
    for (int off = 16; off; off >>= 1)
        s += __shfl_xor_sync(0xffffffffu, s, off);
    if (lane == 0) g_c[warp] = s;
}

// ---------------- k1: u = exp(X @ c); per-block partial column-sums of X ----
// grid (128, 8), block 512 (16 warps, 1 row per warp)
__global__ void k1_u_xsum(const float* __restrict__ X)
{
    const int b    = blockIdx.y;
    const int warp = threadIdx.x >> 5;
    const int lane = threadIdx.x & 31;

    __shared__ float sc[FF];
    __shared__ float sx[16][FF];
    if (threadIdx.x < FF) sc[threadIdx.x] = g_c[threadIdx.x];
    __syncthreads();

    const int row = blockIdx.x * 16 + warp;
    float4 x4 = reinterpret_cast<const float4*>(
                    X + ((size_t)b * NN + row) * FF)[lane];
    float4 c4 = reinterpret_cast<const float4*>(sc)[lane];

    float s = x4.x * c4.x + x4.y * c4.y + x4.z * c4.z + x4.w * c4.w;
#pragma unroll
    for (int off = 16; off; off >>= 1)
        s += __shfl_xor_sync(0xffffffffu, s, off);
    if (lane == 0) g_u[(size_t)b * NN + row] = expf(s);

    reinterpret_cast<float4*>(sx[warp])[lane] = x4;
    __syncthreads();
    if (threadIdx.x < FF) {
        float v = 0.f;
#pragma unroll
        for (int w2 = 0; w2 < 16; w2++) v += sx[w2][threadIdx.x];
        g_xpart[((size_t)b * 128 + blockIdx.x) * FF + threadIdx.x] = v;
    }
}

// ---------------- k3: bits = A!=0; w = A@u (binary => LUT); r = u/w; S ------
// grid (129, 8), block 512. Blocks 0..127: 16 rows each, 8-deep __ldcs
// prefetch, integer nibble extraction (1.0f = 0x3F800000: bit 29), u-LUT
// accumulation (conflict-free LDS.32). Block 128: S path.
__global__ void __launch_bounds__(512) k3_bits_r_S(const float* __restrict__ A,
                                                   const float* __restrict__ W)
{
    const int b = blockIdx.y;

    if (blockIdx.x == 128) {
        // ---- S path: xs = sum over 128 chunks of g_xpart; S = xs @ W ----
        __shared__ float part[4][FF];
        __shared__ float xs[FF];
        __shared__ float dot[4][FF];
        const int t = threadIdx.x & 127;
        const int p = threadIdx.x >> 7;          // 0..3
        float v = 0.f;
#pragma unroll 8
        for (int c = 0; c < 32; c++)
            v += g_xpart[((size_t)b * 128 + p * 32 + c) * FF + t];
        part[p][t] = v;
        __syncthreads();
        if (threadIdx.x < FF)
            xs[t] = part[0][t] + part[1][t] + part[2][t] + part[3][t];
        __syncthreads();
        float s = 0.f;
#pragma unroll 8
        for (int k = 0; k < 32; k++) {
            const int fi = p * 32 + k;
            s += xs[fi] * W[fi * FF + t];
        }
        dot[p][t] = s;
        __syncthreads();
        if (threadIdx.x < FF)
            g_S[b * FF + t] = dot[0][t] + dot[1][t] + dot[2][t] + dot[3][t];
        return;
    }

    // u nibble-LUT: tab[v][G] = sum of u over subset v of columns 4G..4G+3.
    __shared__ float tab[16][512];      // 32 KB
    {
        const int g = threadIdx.x;
        const float4 s = reinterpret_cast<const float4*>(g_u + (size_t)b * NN)[g];
        const float s01 = s.x + s.y;
        const float s23 = s.z + s.w;
        tab[0][g]  = 0.f;          tab[1][g]  = s.x;          tab[2][g]  = s.y;
        tab[3][g]  = s01;          tab[4][g]  = s.z;          tab[5][g]  = s.x + s.z;
        tab[6][g]  = s.y + s.z;    tab[7][g]  = s01 + s.z;    tab[8][g]  = s.w;
        tab[9][g]  = s.x + s.w;    tab[10][g] = s.y + s.w;    tab[11][g] = s01 + s.w;
        tab[12][g] = s23;          tab[13][g] = s.x + s23;    tab[14][g] = s.y + s23;
        tab[15][g] = s01 + s23;
    }
    __syncthreads();

    const int warp = threadIdx.x >> 5;
    const int lane = threadIdx.x & 31;
    const int row  = blockIdx.x * 16 + warp;

    const uint4* Ar = reinterpret_cast<const uint4*>(
                          A + ((size_t)(b * NN + row)) * NN);
    const float* tb = &tab[0][0];

    float acc0 = 0.f, acc1 = 0.f;
    unsigned w0 = 0u, w1 = 0u;

#pragma unroll
    for (int half = 0; half < 2; half++) {
        uint4 v[8];
#pragma unroll
        for (int k = 0; k < 8; k++)          // 8 LDG.128 in flight per warp
            v[k] = __ldcs(&Ar[(half * 8 + k) * 32 + lane]);
#pragma unroll
        for (int k = 0; k < 8; k++) {
            const int j = half * 8 + k;
            // 1.0f = 0x3F800000 (bit 29 set); 0.0f = 0. Pure integer decode.
            unsigned nib = ((v[k].x >> 29) & 1u) | ((v[k].y >> 28) & 2u)
                         | ((v[k].z >> 27) & 4u) | ((v[k].w >> 26) & 8u);
            if (half == 0) { w0 |= nib << (4 * k); acc0 += tb[nib * 512 + j * 32 + lane]; }
            else           { w1 |= nib << (4 * k); acc1 += tb[nib * 512 + j * 32 + lane]; }
        }
    }

    float acc = acc0 + acc1;
#pragma unroll
    for (int off = 16; off; off >>= 1)
        acc += __shfl_xor_sync(0xffffffffu, acc, off);   // w = (A@u)[row]

    unsigned* br = g_bits + ((size_t)(b * NN + row)) * NWRD;
    br[lane]      = w0;    // columns j*128 + lane*4 + {0..3}, j = 0..7
    br[32 + lane] = w1;    // j = 8..15
    if (lane == 0) {
        float u_row = g_u[(size_t)b * NN + row];
        g_r[(size_t)b * NN + row] = (acc != 0.f) ? __fdividef(u_row, acc) : 0.f;
    }
}

// ---------------- k5: q = A @ r via nibble-LUT; H = q*S + bias_W ------------
// grid (32, 8), block 512. Each block: 64 rows (4 per warp).
// tab[v][G], G = j*32 + L: addr = v*512 + j*32 + lane -> bank = lane, CF.
__global__ void __launch_bounds__(512) k5_out(float* __restrict__ H,
                                              const float* __restrict__ biasW)
{
    const int b = blockIdx.y;
    __shared__ float tab[16][512];      // 32 KB, subset-major
    __shared__ float sS[FF];
    __shared__ float sbw[FF];

    if (threadIdx.x < FF) {
        sS[threadIdx.x]  = g_S[b * FF + threadIdx.x];
        sbw[threadIdx.x] = biasW[threadIdx.x];
    }
    {   // build LUT directly from g_r (coalesced float4)
        const int g = threadIdx.x;
        const float4 s = reinterpret_cast<const float4*>(g_r + (size_t)b * NN)[g];
        const float s01 = s.x + s.y;
        const float s23 = s.z + s.w;
        tab[0][g]  = 0.f;          tab[1][g]  = s.x;          tab[2][g]  = s.y;
        tab[3][g]  = s01;          tab[4][g]  = s.z;          tab[5][g]  = s.x + s.z;
        tab[6][g]  = s.y + s.z;    tab[7][g]  = s01 + s.z;    tab[8][g]  = s.w;
        tab[9][g]  = s.x + s.w;    tab[10][g] = s.y + s.w;    tab[11][g] = s01 + s.w;
        tab[12][g] = s23;          tab[13][g] = s.x + s23;    tab[14][g] = s.y + s23;
        tab[15][g] = s01 + s23;
    }
    __syncthreads();

    const int warp = threadIdx.x >> 5;
    const int lane = threadIdx.x & 31;
    const int row0 = blockIdx.x * 64 + warp * 4;     // 4 rows per warp

    const unsigned* bb = g_bits + ((size_t)(b * NN + row0)) * NWRD;
    unsigned rw0[4], rw1[4];
#pragma unroll
    for (int r = 0; r < 4; r++) {
        rw0[r] = bb[r * NWRD + lane];        // half 0: j = 0..7
        rw1[r] = bb[r * NWRD + 32 + lane];   // half 1: j = 8..15
    }

    const float* tb = &tab[0][0];
    float accA[4] = {0.f, 0.f, 0.f, 0.f};
    float accB[4] = {0.f, 0.f, 0.f, 0.f};
#pragma unroll
    for (int j = 0; j < 8; j++) {
        const int base0 = j * 32 + lane;            // G for half 0
        const int base1 = (8 + j) * 32 + lane;      // G for half 1
#pragma unroll
        for (int r = 0; r < 4; r++) {
            accA[r] += tb[((rw0[r] >> (4 * j)) & 15u) * 512 + base0];
            accB[r] += tb[((rw1[r] >> (4 * j)) & 15u) * 512 + base1];
        }
    }

    const float4 s4 = reinterpret_cast<const float4*>(sS)[lane];
    const float4 w4 = reinterpret_cast<const float4*>(sbw)[lane];
#pragma unroll
    for (int r = 0; r < 4; r++) {
        float acc = accA[r] + accB[r];
#pragma unroll
        for (int off = 16; off; off >>= 1)
            acc += __shfl_xor_sync(0xffffffffu, acc, off);   // q[row0+r]
        float4 o;
        o.x = acc * s4.x + w4.x;
        o.y = acc * s4.y + w4.y;
        o.z = acc * s4.z + w4.z;
        o.w = acc * s4.w + w4.w;
        reinterpret_cast<float4*>(H + ((size_t)(b * NN + row0 + r)) * FF)[lane] = o;
    }
}

// ---------------- launch -----------------------------------------------------
extern "C" void kernel_launch(void* const* d_in, const int* in_sizes, int n_in,
                              void* d_out, int out_size)
{
    const float* X     = (const float*)d_in[0];
    const float* A     = (const float*)d_in[1];
    const float* W     = (const float*)d_in[2];
    const float* a     = (const float*)d_in[3];
    // d_in[4] = bias_a: cancels analytically (rank-1 den), unused.
    const float* biasW = (const float*)d_in[5];
    float* H = (float*)d_out;

    k0_c       <<<4, 1024>>>(W, a);
    k1_u_xsum  <<<dim3(128, BB), 512>>>(X);
    k3_bits_r_S<<<dim3(129, BB), 512>>>(A, W);
    k5_out     <<<dim3(32, BB), 512>>>(H, biasW);
}